// round 13
// baseline (speedup 1.0000x reference)
#include <cuda_runtime.h>
#include <cuda_fp16.h>
#include <math.h>
#include <stdint.h>

// ---------------- problem constants ----------------
#define BATCH   4
#define SEQ     4096
#define DIM     1024
#define DI      2048
#define HGCOLS  4096
#define MROWS   16384
#define NCH     8192
#define CHUNK   64
#define NCHUNK  64          // SEQ/CHUNK

// ---------------- scratch ----------------
__device__ float g_hg[(size_t)MROWS * HGCOLS];        // 256 MB
__device__ __half g_xhi[(size_t)MROWS * DIM];
__device__ __half g_whgT[(size_t)HGCOLS * DIM];       // [N,K]
__device__ __half g_woutT[(size_t)DIM * DI];          // [N,K]
__device__ __half g_hhi[(size_t)MROWS * DI];
__device__ float g_A[NCH * NCHUNK];
__device__ float g_M[NCH * NCHUNK];
__device__ float g_W[NCH * NCHUNK];

// ---------------- PTX helpers ----------------
__device__ __forceinline__ uint32_t smem_u32(const void* p) {
    uint32_t a;
    asm("{ .reg .u64 t; cvta.to.shared.u64 t, %1; cvt.u32.u64 %0, t; }" : "=r"(a) : "l"(p));
    return a;
}
__device__ __forceinline__ void cp16(uint32_t dst, const void* src) {
    asm volatile("cp.async.cg.shared.global [%0], [%1], 16;" :: "r"(dst), "l"(src));
}
#define CP_COMMIT() asm volatile("cp.async.commit_group;" ::: "memory")
#define CP_WAIT1()  asm volatile("cp.async.wait_group 1;" ::: "memory")

#define LDSM4(r, a) asm volatile( \
    "ldmatrix.sync.aligned.m8n8.x4.shared.b16 {%0,%1,%2,%3}, [%4];" \
    : "=r"((r)[0]), "=r"((r)[1]), "=r"((r)[2]), "=r"((r)[3]) : "r"(a))
#define LDSM2(r, a) asm volatile( \
    "ldmatrix.sync.aligned.m8n8.x2.shared.b16 {%0,%1}, [%2];" \
    : "=r"((r)[0]), "=r"((r)[1]) : "r"(a))
#define MMA16816(c, a, b) asm volatile( \
    "mma.sync.aligned.m16n8k16.row.col.f32.f16.f16.f32 " \
    "{%0,%1,%2,%3},{%4,%5,%6,%7},{%8,%9},{%0,%1,%2,%3};" \
    : "+f"((c)[0]), "+f"((c)[1]), "+f"((c)[2]), "+f"((c)[3]) \
    : "r"((a)[0]), "r"((a)[1]), "r"((a)[2]), "r"((a)[3]), "r"((b)[0]), "r"((b)[1]))

// ---------------- HMMA GEMM: C[M,N] = A[M,K] @ B[N,K]^T, fp16, BK=64, 3-stage ----------------
#define BM 128
#define BN 128
#define BK 64
#define SSTRIDE_H 72                     // halves per smem row (64 + 8 pad)
#define LIMB_BYTES (128 * SSTRIDE_H * 2) // 18432
#define STAGE_BYTES (2 * LIMB_BYTES)     // A, B = 36864
#define NSTAGE 3
#define GEMM_DYNSMEM (NSTAGE * STAGE_BYTES)  // 110592

__global__ __launch_bounds__(256, 2)
void hmma_gemm(const __half* __restrict__ Ahi,
               const __half* __restrict__ Bhi,
               float* __restrict__ C, int N, int K) {
    extern __shared__ char dynsmem[];
    const uint32_t sbase = smem_u32(dynsmem);

    const int tid  = threadIdx.x;
    const int wid  = tid >> 5;
    const int lane = tid & 31;
    const int wm   = wid >> 2;
    const int wn   = wid & 3;
    const int m0   = blockIdx.y * BM;
    const int n0   = blockIdx.x * BN;
    const int NI   = K / BK;

    const int arow_l = (lane & 7) + ((lane & 8) ? 8 : 0);
    const int acol_l = (lane >> 4) * 8;
    const int blane  = lane & 15;
    const int brow_l = blane & 7;
    const int bcol_l = (blane >> 3) * 8;

    float acc[4][4][4];
    #pragma unroll
    for (int i = 0; i < 4; i++)
        #pragma unroll
        for (int j = 0; j < 4; j++)
            #pragma unroll
            for (int q = 0; q < 4; q++) acc[i][j][q] = 0.f;

    auto prefetch = [&](int it, int s) {
        const uint32_t sb = sbase + s * STAGE_BYTES;
        const int kt = it * BK;
        #pragma unroll
        for (int t = tid; t < 1024; t += 256) {
            const int row = t >> 3;          // 0..127
            const int seg = t & 7;           // 8 x 16B = 128B = 64 halves
            const uint32_t so = (uint32_t)(row * (SSTRIDE_H * 2) + seg * 16);
            const size_t ga = (size_t)(m0 + row) * K + kt + seg * 8;
            const size_t gb = (size_t)(n0 + row) * K + kt + seg * 8;
            cp16(sb + so,              Ahi + ga);
            cp16(sb + LIMB_BYTES + so, Bhi + gb);
        }
        CP_COMMIT();
    };

    prefetch(0, 0);
    if (NI > 1) prefetch(1, 1);

    int s = 0;
    for (int it = 0; it < NI; it++) {
        CP_WAIT1();          // group 'it' complete; group 'it+1' may stay in flight
        __syncthreads();     // all warps done with iter it-1 -> stage (it+2)%3 free
        if (it + 2 < NI) prefetch(it + 2, (s + 2 >= NSTAGE) ? s + 2 - NSTAGE : s + 2);

        const uint32_t sAh = sbase + s * STAGE_BYTES;
        const uint32_t sBh = sAh + LIMB_BYTES;

        #pragma unroll
        for (int ks = 0; ks < 4; ks++) {
            uint32_t af[4][4], bh[4][2];
            #pragma unroll
            for (int mf = 0; mf < 4; mf++) {
                const uint32_t ao =
                    (uint32_t)((wm * 64 + mf * 16 + arow_l) * (SSTRIDE_H * 2) +
                               (ks * 16 + acol_l) * 2);
                LDSM4(af[mf], sAh + ao);
            }
            #pragma unroll
            for (int nf = 0; nf < 4; nf++) {
                const uint32_t bo =
                    (uint32_t)((wn * 32 + nf * 8 + brow_l) * (SSTRIDE_H * 2) +
                               (ks * 16 + bcol_l) * 2);
                LDSM2(bh[nf], sBh + bo);
            }
            #pragma unroll
            for (int mf = 0; mf < 4; mf++)
                #pragma unroll
                for (int nf = 0; nf < 4; nf++) MMA16816(acc[mf][nf], af[mf], bh[nf]);
        }
        s = (s + 1 >= NSTAGE) ? 0 : s + 1;
    }

    // epilogue
    #pragma unroll
    for (int mf = 0; mf < 4; mf++) {
        const int r0 = m0 + wm * 64 + mf * 16 + lane / 4;
        #pragma unroll
        for (int nf = 0; nf < 4; nf++) {
            const int col = n0 + wn * 32 + nf * 8 + 2 * (lane % 4);
            *(float2*)(C + (size_t)r0 * N + col) =
                make_float2(acc[mf][nf][0], acc[mf][nf][1]);
            *(float2*)(C + (size_t)(r0 + 8) * N + col) =
                make_float2(acc[mf][nf][2], acc[mf][nf][3]);
        }
    }
}

// ---------------- prep ----------------
__global__ __launch_bounds__(256)
void cast_hi(const float* __restrict__ in, __half* __restrict__ hi, int n) {
    int i = blockIdx.x * blockDim.x + threadIdx.x;
    if (i >= n) return;
    hi[i] = __float2half_rn(in[i]);
}

// W[K,N] row-major -> out[N,K] row-major fp16, 32x32 smem tiles
__global__ __launch_bounds__(256)
void transpose_cast_tiled(const float* __restrict__ W, __half* __restrict__ hi,
                          int K, int N) {
    __shared__ float tile[32][33];
    const int k0 = blockIdx.y * 32;
    const int n0 = blockIdx.x * 32;
    const int tx = threadIdx.x & 31;
    const int ty = threadIdx.x >> 5;   // 0..7

    #pragma unroll
    for (int r = 0; r < 4; r++) {
        const int k = k0 + ty + r * 8;
        tile[ty + r * 8][tx] = W[(size_t)k * N + n0 + tx];
    }
    __syncthreads();
    #pragma unroll
    for (int r = 0; r < 4; r++) {
        const int n = n0 + ty + r * 8;
        hi[(size_t)n * K + k0 + tx] = __float2half_rn(tile[tx][ty + r * 8]);
    }
}

// ---------------- scan (scalar; CHUNK=64 for 2x thread parallelism) ----------------
__device__ __forceinline__ void minGRU_terms(float hid, float g, float& lc, float& lv) {
    float sp = log1pf(__expf(-fabsf(g))) + fmaxf(g, 0.f);
    lc = -sp;
    float log_z = g - sp;
    lv = __logf(fmaxf(hid, 0.f) + 0.5f) + log_z;
}

__global__ __launch_bounds__(256)
void scan_pass1() {
    int tid = blockIdx.x * blockDim.x + threadIdx.x;
    int e = tid % DI;
    int c = (tid / DI) % NCHUNK;
    int b = tid / (DI * NCHUNK);

    const float* base = g_hg + ((size_t)(b * SEQ + c * CHUNK)) * HGCOLS + e;
    float a = 0.f, m = -INFINITY, s = 0.f;
    for (int t = 0; t < CHUNK; t++) {
        float hid = base[(size_t)t * HGCOLS];
        float g   = base[(size_t)t * HGCOLS + DI];
        float lc, lv;
        minGRU_terms(hid, g, lc, lv);
        a += lc;
        float v = lv - a;
        if (v <= m) {
            s += __expf(v - m);
        } else {
            s = s * __expf(m - v) + 1.f;
            m = v;
        }
    }
    int o = (b * NCHUNK + c) * DI + e;
    g_A[o] = a;
    g_M[o] = m + __logf(s);
}

__global__ __launch_bounds__(256)
void scan_mid() {
    int tid = blockIdx.x * blockDim.x + threadIdx.x;
    int e = tid % DI;
    int b = tid / DI;
    float W = -INFINITY;
    for (int c = 0; c < NCHUNK; c++) {
        int o = (b * NCHUNK + c) * DI + e;
        g_W[o] = W;
        float A = g_A[o], M = g_M[o];
        float mx = fmaxf(W, M);
        float mn = fminf(W, M);
        float r = (mx == -INFINITY) ? -INFINITY : mx + log1pf(__expf(mn - mx));
        W = A + r;
    }
}

__global__ __launch_bounds__(256)
void scan_pass2() {
    int tid = blockIdx.x * blockDim.x + threadIdx.x;
    int e = tid % DI;
    int c = (tid / DI) % NCHUNK;
    int b = tid / (DI * NCHUNK);

    const float* base = g_hg + ((size_t)(b * SEQ + c * CHUNK)) * HGCOLS + e;
    size_t hidx = ((size_t)(b * SEQ + c * CHUNK)) * DI + e;
    float W = g_W[(b * NCHUNK + c) * DI + e];

    float a = 0.f, m = -INFINITY, s = 0.f;
    for (int t = 0; t < CHUNK; t++) {
        float hid = base[(size_t)t * HGCOLS];
        float g   = base[(size_t)t * HGCOLS + DI];
        float lc, lv;
        minGRU_terms(hid, g, lc, lv);
        a += lc;
        float v = lv - a;
        if (v <= m) {
            s += __expf(v - m);
        } else {
            s = s * __expf(m - v) + 1.f;
            m = v;
        }
        float hv = __expf(a + W) + __expf(a + m) * s;
        g_hhi[hidx + (size_t)t * DI] = __float2half_rn(hv);
    }
}

// ---------------- launch ----------------
extern "C" void kernel_launch(void* const* d_in, const int* in_sizes, int n_in,
                              void* d_out, int out_size) {
    const float* x     = (const float*)d_in[0];
    const float* W_hg  = (const float*)d_in[1];
    const float* W_out = (const float*)d_in[2];
    float* out = (float*)d_out;

    float* hg_ptr;
    __half *xhi, *whgT, *woutT, *hhi;
    cudaGetSymbolAddress((void**)&hg_ptr, g_hg);
    cudaGetSymbolAddress((void**)&xhi, g_xhi);
    cudaGetSymbolAddress((void**)&whgT, g_whgT);
    cudaGetSymbolAddress((void**)&woutT, g_woutT);
    cudaGetSymbolAddress((void**)&hhi, g_hhi);

    cudaFuncSetAttribute(hmma_gemm, cudaFuncAttributeMaxDynamicSharedMemorySize, GEMM_DYNSMEM);

    cast_hi<<<(MROWS * DIM + 255) / 256, 256>>>(x, xhi, MROWS * DIM);
    {
        dim3 g1(HGCOLS / 32, DIM / 32);
        transpose_cast_tiled<<<g1, 256>>>(W_hg, whgT, DIM, HGCOLS);
        dim3 g2(DIM / 32, DI / 32);
        transpose_cast_tiled<<<g2, 256>>>(W_out, woutT, DI, DIM);
    }

    // GEMM1: hg[16384,4096] = x @ W_hg
    {
        dim3 grid(HGCOLS / BN, MROWS / BM);
        hmma_gemm<<<grid, 256, GEMM_DYNSMEM>>>(xhi, whgT, hg_ptr, HGCOLS, DIM);
    }

    scan_pass1<<<(NCH * NCHUNK) / 256, 256>>>();
    scan_mid<<<NCH / 256, 256>>>();
    scan_pass2<<<(NCH * NCHUNK) / 256, 256>>>();

    // GEMM2: out[16384,1024] = h @ W_out
    {
        dim3 grid(DIM / BN, MROWS / BM);
        hmma_gemm<<<grid, 256, GEMM_DYNSMEM>>>(hhi, woutT, out, DIM, DI);
    }
}

// round 14
// speedup vs baseline: 1.5353x; 1.5353x over previous
#include <cuda_runtime.h>
#include <cuda_fp16.h>
#include <math.h>
#include <stdint.h>

// ---------------- problem constants ----------------
#define BATCH   4
#define SEQ     4096
#define DIM     1024
#define DI      2048
#define HGCOLS  4096
#define MROWS   16384
#define NCH     8192
#define CHUNK   128
#define NCHUNK  32

// ---------------- scratch ----------------
__device__ __half g_hg[(size_t)MROWS * HGCOLS];       // 128 MB (fp16 now)
__device__ __half g_xhi[(size_t)MROWS * DIM];
__device__ __half g_whgT[(size_t)HGCOLS * DIM];       // [N,K]
__device__ __half g_woutT[(size_t)DIM * DI];          // [N,K]
__device__ __half g_hhi[(size_t)MROWS * DI];
__device__ float g_A[NCH * NCHUNK];
__device__ float g_M[NCH * NCHUNK];
__device__ float g_W[NCH * NCHUNK];

// ---------------- PTX helpers ----------------
__device__ __forceinline__ uint32_t smem_u32(const void* p) {
    uint32_t a;
    asm("{ .reg .u64 t; cvta.to.shared.u64 t, %1; cvt.u32.u64 %0, t; }" : "=r"(a) : "l"(p));
    return a;
}
__device__ __forceinline__ void cp16(uint32_t dst, const void* src) {
    asm volatile("cp.async.cg.shared.global [%0], [%1], 16;" :: "r"(dst), "l"(src));
}
#define CP_COMMIT() asm volatile("cp.async.commit_group;" ::: "memory")
#define CP_WAIT0()  asm volatile("cp.async.wait_group 0;" ::: "memory")

#define LDSM4(r, a) asm volatile( \
    "ldmatrix.sync.aligned.m8n8.x4.shared.b16 {%0,%1,%2,%3}, [%4];" \
    : "=r"((r)[0]), "=r"((r)[1]), "=r"((r)[2]), "=r"((r)[3]) : "r"(a))
#define LDSM2(r, a) asm volatile( \
    "ldmatrix.sync.aligned.m8n8.x2.shared.b16 {%0,%1}, [%2];" \
    : "=r"((r)[0]), "=r"((r)[1]) : "r"(a))
#define MMA16816(c, a, b) asm volatile( \
    "mma.sync.aligned.m16n8k16.row.col.f32.f16.f16.f32 " \
    "{%0,%1,%2,%3},{%4,%5,%6,%7},{%8,%9},{%0,%1,%2,%3};" \
    : "+f"((c)[0]), "+f"((c)[1]), "+f"((c)[2]), "+f"((c)[3]) \
    : "r"((a)[0]), "r"((a)[1]), "r"((a)[2]), "r"((a)[3]), "r"((b)[0]), "r"((b)[1]))

// ---------------- HMMA GEMM (R12-proven): C = A[M,K] @ B[N,K]^T, BK=64, 2-stage ----------------
#define BM 128
#define BN 128
#define BK 64
#define SSTRIDE_H 72                     // halves per smem row (64 + 8 pad)
#define LIMB_BYTES (128 * SSTRIDE_H * 2) // 18432
#define STAGE_BYTES (2 * LIMB_BYTES)     // A, B = 36864
#define GEMM_DYNSMEM (2 * STAGE_BYTES)   // 73728

template <typename OutT>
__global__ __launch_bounds__(256, 2)
void hmma_gemm(const __half* __restrict__ Ahi,
               const __half* __restrict__ Bhi,
               OutT* __restrict__ C, int N, int K) {
    extern __shared__ char dynsmem[];
    const uint32_t sbase = smem_u32(dynsmem);

    const int tid  = threadIdx.x;
    const int wid  = tid >> 5;
    const int lane = tid & 31;
    const int wm   = wid >> 2;
    const int wn   = wid & 3;
    const int m0   = blockIdx.y * BM;
    const int n0   = blockIdx.x * BN;
    const int NI   = K / BK;

    const int arow_l = (lane & 7) + ((lane & 8) ? 8 : 0);
    const int acol_l = (lane >> 4) * 8;
    const int blane  = lane & 15;
    const int brow_l = blane & 7;
    const int bcol_l = (blane >> 3) * 8;

    float acc[4][4][4];
    #pragma unroll
    for (int i = 0; i < 4; i++)
        #pragma unroll
        for (int j = 0; j < 4; j++)
            #pragma unroll
            for (int q = 0; q < 4; q++) acc[i][j][q] = 0.f;

    auto prefetch = [&](int it, int s) {
        const uint32_t sb = sbase + s * STAGE_BYTES;
        const int kt = it * BK;
        #pragma unroll
        for (int t = tid; t < 1024; t += 256) {
            const int row = t >> 3;
            const int seg = t & 7;
            const uint32_t so = (uint32_t)(row * (SSTRIDE_H * 2) + seg * 16);
            const size_t ga = (size_t)(m0 + row) * K + kt + seg * 8;
            const size_t gb = (size_t)(n0 + row) * K + kt + seg * 8;
            cp16(sb + so,              Ahi + ga);
            cp16(sb + LIMB_BYTES + so, Bhi + gb);
        }
        CP_COMMIT();
    };

    prefetch(0, 0);

    for (int it = 0; it < NI; it++) {
        const int s = it & 1;
        CP_WAIT0();
        __syncthreads();
        if (it + 1 < NI) prefetch(it + 1, s ^ 1);

        const uint32_t sAh = sbase + s * STAGE_BYTES;
        const uint32_t sBh = sAh + LIMB_BYTES;

        #pragma unroll
        for (int ks = 0; ks < 4; ks++) {
            uint32_t af[4][4], bh[4][2];
            #pragma unroll
            for (int mf = 0; mf < 4; mf++) {
                const uint32_t ao =
                    (uint32_t)((wm * 64 + mf * 16 + arow_l) * (SSTRIDE_H * 2) +
                               (ks * 16 + acol_l) * 2);
                LDSM4(af[mf], sAh + ao);
            }
            #pragma unroll
            for (int nf = 0; nf < 4; nf++) {
                const uint32_t bo =
                    (uint32_t)((wn * 32 + nf * 8 + brow_l) * (SSTRIDE_H * 2) +
                               (ks * 16 + bcol_l) * 2);
                LDSM2(bh[nf], sBh + bo);
            }
            #pragma unroll
            for (int mf = 0; mf < 4; mf++)
                #pragma unroll
                for (int nf = 0; nf < 4; nf++) MMA16816(acc[mf][nf], af[mf], bh[nf]);
        }
    }

    // epilogue
    #pragma unroll
    for (int mf = 0; mf < 4; mf++) {
        const int r0 = m0 + wm * 64 + mf * 16 + lane / 4;
        #pragma unroll
        for (int nf = 0; nf < 4; nf++) {
            const int col = n0 + wn * 32 + nf * 8 + 2 * (lane % 4);
            if (sizeof(OutT) == 4) {
                *(float2*)((float*)C + (size_t)r0 * N + col) =
                    make_float2(acc[mf][nf][0], acc[mf][nf][1]);
                *(float2*)((float*)C + (size_t)(r0 + 8) * N + col) =
                    make_float2(acc[mf][nf][2], acc[mf][nf][3]);
            } else {
                __half2 p0 = __float22half2_rn(make_float2(acc[mf][nf][0], acc[mf][nf][1]));
                __half2 p1 = __float22half2_rn(make_float2(acc[mf][nf][2], acc[mf][nf][3]));
                *(__half2*)((__half*)C + (size_t)r0 * N + col) = p0;
                *(__half2*)((__half*)C + (size_t)(r0 + 8) * N + col) = p1;
            }
        }
    }
}

// ---------------- prep ----------------
__global__ __launch_bounds__(256)
void cast_hi(const float* __restrict__ in, __half* __restrict__ hi, int n) {
    int i = blockIdx.x * blockDim.x + threadIdx.x;
    if (i >= n) return;
    hi[i] = __float2half_rn(in[i]);
}

__global__ __launch_bounds__(256)
void transpose_cast_tiled(const float* __restrict__ W, __half* __restrict__ hi,
                          int K, int N) {
    __shared__ float tile[32][33];
    const int k0 = blockIdx.y * 32;
    const int n0 = blockIdx.x * 32;
    const int tx = threadIdx.x & 31;
    const int ty = threadIdx.x >> 5;

    #pragma unroll
    for (int r = 0; r < 4; r++) {
        const int k = k0 + ty + r * 8;
        tile[ty + r * 8][tx] = W[(size_t)k * N + n0 + tx];
    }
    __syncthreads();
    #pragma unroll
    for (int r = 0; r < 4; r++) {
        const int n = n0 + ty + r * 8;
        hi[(size_t)n * K + k0 + tx] = __float2half_rn(tile[tx][ty + r * 8]);
    }
}

// ---------------- scan (scalar, CHUNK=128 proven; reads fp16 hg) ----------------
__device__ __forceinline__ void minGRU_terms(float hid, float g, float& lc, float& lv) {
    float sp = log1pf(__expf(-fabsf(g))) + fmaxf(g, 0.f);
    lc = -sp;
    float log_z = g - sp;
    lv = __logf(fmaxf(hid, 0.f) + 0.5f) + log_z;
}

__global__ __launch_bounds__(256)
void scan_pass1() {
    int tid = blockIdx.x * blockDim.x + threadIdx.x;
    int e = tid % DI;
    int c = (tid / DI) % NCHUNK;
    int b = tid / (DI * NCHUNK);

    const __half* base = g_hg + ((size_t)(b * SEQ + c * CHUNK)) * HGCOLS + e;
    float a = 0.f, m = -INFINITY, s = 0.f;
    for (int t = 0; t < CHUNK; t++) {
        float hid = __half2float(__ldg(base + (size_t)t * HGCOLS));
        float g   = __half2float(__ldg(base + (size_t)t * HGCOLS + DI));
        float lc, lv;
        minGRU_terms(hid, g, lc, lv);
        a += lc;
        float v = lv - a;
        if (v <= m) {
            s += __expf(v - m);
        } else {
            s = s * __expf(m - v) + 1.f;
            m = v;
        }
    }
    int o = (b * NCHUNK + c) * DI + e;
    g_A[o] = a;
    g_M[o] = m + __logf(s);
}

__global__ __launch_bounds__(256)
void scan_mid() {
    int tid = blockIdx.x * blockDim.x + threadIdx.x;
    int e = tid % DI;
    int b = tid / DI;
    float W = -INFINITY;
    for (int c = 0; c < NCHUNK; c++) {
        int o = (b * NCHUNK + c) * DI + e;
        g_W[o] = W;
        float A = g_A[o], M = g_M[o];
        float mx = fmaxf(W, M);
        float mn = fminf(W, M);
        float r = (mx == -INFINITY) ? -INFINITY : mx + log1pf(__expf(mn - mx));
        W = A + r;
    }
}

__global__ __launch_bounds__(256)
void scan_pass2() {
    int tid = blockIdx.x * blockDim.x + threadIdx.x;
    int e = tid % DI;
    int c = (tid / DI) % NCHUNK;
    int b = tid / (DI * NCHUNK);

    const __half* base = g_hg + ((size_t)(b * SEQ + c * CHUNK)) * HGCOLS + e;
    size_t hidx = ((size_t)(b * SEQ + c * CHUNK)) * DI + e;
    float W = g_W[(b * NCHUNK + c) * DI + e];

    float a = 0.f, m = -INFINITY, s = 0.f;
    for (int t = 0; t < CHUNK; t++) {
        float hid = __half2float(__ldg(base + (size_t)t * HGCOLS));
        float g   = __half2float(__ldg(base + (size_t)t * HGCOLS + DI));
        float lc, lv;
        minGRU_terms(hid, g, lc, lv);
        a += lc;
        float v = lv - a;
        if (v <= m) {
            s += __expf(v - m);
        } else {
            s = s * __expf(m - v) + 1.f;
            m = v;
        }
        float hv = __expf(a + W) + __expf(a + m) * s;
        g_hhi[hidx + (size_t)t * DI] = __float2half_rn(hv);
    }
}

// ---------------- launch ----------------
extern "C" void kernel_launch(void* const* d_in, const int* in_sizes, int n_in,
                              void* d_out, int out_size) {
    const float* x     = (const float*)d_in[0];
    const float* W_hg  = (const float*)d_in[1];
    const float* W_out = (const float*)d_in[2];
    float* out = (float*)d_out;

    __half *hg_ptr, *xhi, *whgT, *woutT, *hhi;
    cudaGetSymbolAddress((void**)&hg_ptr, g_hg);
    cudaGetSymbolAddress((void**)&xhi, g_xhi);
    cudaGetSymbolAddress((void**)&whgT, g_whgT);
    cudaGetSymbolAddress((void**)&woutT, g_woutT);
    cudaGetSymbolAddress((void**)&hhi, g_hhi);

    cudaFuncSetAttribute(hmma_gemm<__half>, cudaFuncAttributeMaxDynamicSharedMemorySize, GEMM_DYNSMEM);
    cudaFuncSetAttribute(hmma_gemm<float>,  cudaFuncAttributeMaxDynamicSharedMemorySize, GEMM_DYNSMEM);

    cast_hi<<<(MROWS * DIM + 255) / 256, 256>>>(x, xhi, MROWS * DIM);
    {
        dim3 g1(HGCOLS / 32, DIM / 32);
        transpose_cast_tiled<<<g1, 256>>>(W_hg, whgT, DIM, HGCOLS);
        dim3 g2(DIM / 32, DI / 32);
        transpose_cast_tiled<<<g2, 256>>>(W_out, woutT, DI, DIM);
    }

    // GEMM1: hg[16384,4096] = x @ W_hg   (fp16 output)
    {
        dim3 grid(HGCOLS / BN, MROWS / BM);
        hmma_gemm<__half><<<grid, 256, GEMM_DYNSMEM>>>(xhi, whgT, hg_ptr, HGCOLS, DIM);
    }

    scan_pass1<<<(NCH * NCHUNK) / 256, 256>>>();
    scan_mid<<<NCH / 256, 256>>>();
    scan_pass2<<<(NCH * NCHUNK) / 256, 256>>>();

    // GEMM2: out[16384,1024] = h @ W_out  (fp32 output)
    {
        dim3 grid(DIM / BN, MROWS / BM);
        hmma_gemm<float><<<grid, 256, GEMM_DYNSMEM>>>(hhi, woutT, out, DIM, DI);
    }
}

// round 15
// speedup vs baseline: 1.5816x; 1.0301x over previous
#include <cuda_runtime.h>
#include <cuda_fp16.h>
#include <math.h>
#include <stdint.h>

// ---------------- problem constants ----------------
#define BATCH   4
#define SEQ     4096
#define DIM     1024
#define DI      2048
#define HGCOLS  4096
#define MROWS   16384
#define NCH     8192
#define CHUNK   128
#define NCHUNK  32

// ---------------- scratch ----------------
__device__ __half g_hg[(size_t)MROWS * HGCOLS];       // 128 MB, interleaved (h,g) pairs
__device__ __half g_xhi[(size_t)MROWS * DIM];
__device__ __half g_whgT[(size_t)HGCOLS * DIM];       // [N,K], N-rows permuted for interleave
__device__ __half g_woutT[(size_t)DIM * DI];          // [N,K]
__device__ __half g_hhi[(size_t)MROWS * DI];
__device__ float g_A[NCH * NCHUNK];
__device__ float g_M[NCH * NCHUNK];
__device__ float g_W[NCH * NCHUNK];

// ---------------- PTX helpers ----------------
__device__ __forceinline__ uint32_t smem_u32(const void* p) {
    uint32_t a;
    asm("{ .reg .u64 t; cvta.to.shared.u64 t, %1; cvt.u32.u64 %0, t; }" : "=r"(a) : "l"(p));
    return a;
}
__device__ __forceinline__ void cp16(uint32_t dst, const void* src) {
    asm volatile("cp.async.cg.shared.global [%0], [%1], 16;" :: "r"(dst), "l"(src));
}
#define CP_COMMIT() asm volatile("cp.async.commit_group;" ::: "memory")
#define CP_WAIT0()  asm volatile("cp.async.wait_group 0;" ::: "memory")

#define LDSM4(r, a) asm volatile( \
    "ldmatrix.sync.aligned.m8n8.x4.shared.b16 {%0,%1,%2,%3}, [%4];" \
    : "=r"((r)[0]), "=r"((r)[1]), "=r"((r)[2]), "=r"((r)[3]) : "r"(a))
#define LDSM2(r, a) asm volatile( \
    "ldmatrix.sync.aligned.m8n8.x2.shared.b16 {%0,%1}, [%2];" \
    : "=r"((r)[0]), "=r"((r)[1]) : "r"(a))
#define MMA16816(c, a, b) asm volatile( \
    "mma.sync.aligned.m16n8k16.row.col.f32.f16.f16.f32 " \
    "{%0,%1,%2,%3},{%4,%5,%6,%7},{%8,%9},{%0,%1,%2,%3};" \
    : "+f"((c)[0]), "+f"((c)[1]), "+f"((c)[2]), "+f"((c)[3]) \
    : "r"((a)[0]), "r"((a)[1]), "r"((a)[2]), "r"((a)[3]), "r"((b)[0]), "r"((b)[1]))

// ---------------- HMMA GEMM (R12-proven): C = A[M,K] @ B[N,K]^T, BK=64, 2-stage ----------------
#define BM 128
#define BN 128
#define BK 64
#define SSTRIDE_H 72                     // halves per smem row (64 + 8 pad)
#define LIMB_BYTES (128 * SSTRIDE_H * 2) // 18432
#define STAGE_BYTES (2 * LIMB_BYTES)     // A, B = 36864
#define GEMM_DYNSMEM (2 * STAGE_BYTES)   // 73728

template <typename OutT>
__global__ __launch_bounds__(256, 2)
void hmma_gemm(const __half* __restrict__ Ahi,
               const __half* __restrict__ Bhi,
               OutT* __restrict__ C, int N, int K) {
    extern __shared__ char dynsmem[];
    const uint32_t sbase = smem_u32(dynsmem);

    const int tid  = threadIdx.x;
    const int wid  = tid >> 5;
    const int lane = tid & 31;
    const int wm   = wid >> 2;
    const int wn   = wid & 3;
    const int m0   = blockIdx.y * BM;
    const int n0   = blockIdx.x * BN;
    const int NI   = K / BK;

    const int arow_l = (lane & 7) + ((lane & 8) ? 8 : 0);
    const int acol_l = (lane >> 4) * 8;
    const int blane  = lane & 15;
    const int brow_l = blane & 7;
    const int bcol_l = (blane >> 3) * 8;

    float acc[4][4][4];
    #pragma unroll
    for (int i = 0; i < 4; i++)
        #pragma unroll
        for (int j = 0; j < 4; j++)
            #pragma unroll
            for (int q = 0; q < 4; q++) acc[i][j][q] = 0.f;

    auto prefetch = [&](int it, int s) {
        const uint32_t sb = sbase + s * STAGE_BYTES;
        const int kt = it * BK;
        #pragma unroll
        for (int t = tid; t < 1024; t += 256) {
            const int row = t >> 3;
            const int seg = t & 7;
            const uint32_t so = (uint32_t)(row * (SSTRIDE_H * 2) + seg * 16);
            const size_t ga = (size_t)(m0 + row) * K + kt + seg * 8;
            const size_t gb = (size_t)(n0 + row) * K + kt + seg * 8;
            cp16(sb + so,              Ahi + ga);
            cp16(sb + LIMB_BYTES + so, Bhi + gb);
        }
        CP_COMMIT();
    };

    prefetch(0, 0);

    for (int it = 0; it < NI; it++) {
        const int s = it & 1;
        CP_WAIT0();
        __syncthreads();
        if (it + 1 < NI) prefetch(it + 1, s ^ 1);

        const uint32_t sAh = sbase + s * STAGE_BYTES;
        const uint32_t sBh = sAh + LIMB_BYTES;

        #pragma unroll
        for (int ks = 0; ks < 4; ks++) {
            uint32_t af[4][4], bh[4][2];
            #pragma unroll
            for (int mf = 0; mf < 4; mf++) {
                const uint32_t ao =
                    (uint32_t)((wm * 64 + mf * 16 + arow_l) * (SSTRIDE_H * 2) +
                               (ks * 16 + acol_l) * 2);
                LDSM4(af[mf], sAh + ao);
            }
            #pragma unroll
            for (int nf = 0; nf < 4; nf++) {
                const uint32_t bo =
                    (uint32_t)((wn * 32 + nf * 8 + brow_l) * (SSTRIDE_H * 2) +
                               (ks * 16 + bcol_l) * 2);
                LDSM2(bh[nf], sBh + bo);
            }
            #pragma unroll
            for (int mf = 0; mf < 4; mf++)
                #pragma unroll
                for (int nf = 0; nf < 4; nf++) MMA16816(acc[mf][nf], af[mf], bh[nf]);
        }
    }

    // epilogue
    #pragma unroll
    for (int mf = 0; mf < 4; mf++) {
        const int r0 = m0 + wm * 64 + mf * 16 + lane / 4;
        #pragma unroll
        for (int nf = 0; nf < 4; nf++) {
            const int col = n0 + wn * 32 + nf * 8 + 2 * (lane % 4);
            if (sizeof(OutT) == 4) {
                *(float2*)((float*)C + (size_t)r0 * N + col) =
                    make_float2(acc[mf][nf][0], acc[mf][nf][1]);
                *(float2*)((float*)C + (size_t)(r0 + 8) * N + col) =
                    make_float2(acc[mf][nf][2], acc[mf][nf][3]);
            } else {
                __half2 p0 = __float22half2_rn(make_float2(acc[mf][nf][0], acc[mf][nf][1]));
                __half2 p1 = __float22half2_rn(make_float2(acc[mf][nf][2], acc[mf][nf][3]));
                *(__half2*)((__half*)C + (size_t)r0 * N + col) = p0;
                *(__half2*)((__half*)C + (size_t)(r0 + 8) * N + col) = p1;
            }
        }
    }
}

// ---------------- prep ----------------
__global__ __launch_bounds__(256)
void cast_hi(const float* __restrict__ in, __half* __restrict__ hi, int n) {
    int i = blockIdx.x * blockDim.x + threadIdx.x;
    if (i >= n) return;
    hi[i] = __float2half_rn(in[i]);
}

// Generic transpose: W[K,N] -> out[N,K] fp16.
// PERM != 0 applies the hidden/gate interleave permutation to the output row:
//   n < N/2  (hidden col e)  -> row 2e
//   n >= N/2 (gate col e)    -> row 2e+1
template <int PERM>
__global__ __launch_bounds__(256)
void transpose_cast_tiled(const float* __restrict__ W, __half* __restrict__ hi,
                          int K, int N) {
    __shared__ float tile[32][33];
    const int k0 = blockIdx.y * 32;
    const int n0 = blockIdx.x * 32;
    const int tx = threadIdx.x & 31;
    const int ty = threadIdx.x >> 5;

    #pragma unroll
    for (int r = 0; r < 4; r++) {
        const int k = k0 + ty + r * 8;
        tile[ty + r * 8][tx] = W[(size_t)k * N + n0 + tx];
    }
    __syncthreads();
    #pragma unroll
    for (int r = 0; r < 4; r++) {
        const int n = n0 + ty + r * 8;
        int p = n;
        if (PERM) p = (n < N / 2) ? (2 * n) : (2 * (n - N / 2) + 1);
        hi[(size_t)p * K + k0 + tx] = __float2half_rn(tile[tx][ty + r * 8]);
    }
}

// ---------------- scan: interleaved (h,g) pairs, one half2 load per step ----------------
__device__ __forceinline__ void minGRU_terms(float hid, float g, float& lc, float& lv) {
    float sp = log1pf(__expf(-fabsf(g))) + fmaxf(g, 0.f);
    lc = -sp;
    float log_z = g - sp;
    lv = __logf(fmaxf(hid, 0.f) + 0.5f) + log_z;
}

__global__ __launch_bounds__(256)
void scan_pass1() {
    int tid = blockIdx.x * blockDim.x + threadIdx.x;
    int e = tid % DI;
    int c = (tid / DI) % NCHUNK;
    int b = tid / (DI * NCHUNK);

    const __half2* base =
        (const __half2*)(g_hg + ((size_t)(b * SEQ + c * CHUNK)) * HGCOLS + 2 * e);
    float a = 0.f, m = -INFINITY, s = 0.f;
    #pragma unroll 4
    for (int t = 0; t < CHUNK; t++) {
        float2 hgv = __half22float2(__ldg(base + (size_t)t * (HGCOLS / 2)));
        float lc, lv;
        minGRU_terms(hgv.x, hgv.y, lc, lv);
        a += lc;
        float v = lv - a;
        if (v <= m) {
            s += __expf(v - m);
        } else {
            s = s * __expf(m - v) + 1.f;
            m = v;
        }
    }
    int o = (b * NCHUNK + c) * DI + e;
    g_A[o] = a;
    g_M[o] = m + __logf(s);
}

__global__ __launch_bounds__(256)
void scan_mid() {
    int tid = blockIdx.x * blockDim.x + threadIdx.x;
    int e = tid % DI;
    int b = tid / DI;
    float W = -INFINITY;
    for (int c = 0; c < NCHUNK; c++) {
        int o = (b * NCHUNK + c) * DI + e;
        g_W[o] = W;
        float A = g_A[o], M = g_M[o];
        float mx = fmaxf(W, M);
        float mn = fminf(W, M);
        float r = (mx == -INFINITY) ? -INFINITY : mx + log1pf(__expf(mn - mx));
        W = A + r;
    }
}

__global__ __launch_bounds__(256)
void scan_pass2() {
    int tid = blockIdx.x * blockDim.x + threadIdx.x;
    int e = tid % DI;
    int c = (tid / DI) % NCHUNK;
    int b = tid / (DI * NCHUNK);

    const __half2* base =
        (const __half2*)(g_hg + ((size_t)(b * SEQ + c * CHUNK)) * HGCOLS + 2 * e);
    size_t hidx = ((size_t)(b * SEQ + c * CHUNK)) * DI + e;
    float W = g_W[(b * NCHUNK + c) * DI + e];

    float a = 0.f, m = -INFINITY, s = 0.f;
    #pragma unroll 4
    for (int t = 0; t < CHUNK; t++) {
        float2 hgv = __half22float2(__ldg(base + (size_t)t * (HGCOLS / 2)));
        float lc, lv;
        minGRU_terms(hgv.x, hgv.y, lc, lv);
        a += lc;
        float v = lv - a;
        if (v <= m) {
            s += __expf(v - m);
        } else {
            s = s * __expf(m - v) + 1.f;
            m = v;
        }
        float hv = __expf(a + W) + __expf(a + m) * s;
        g_hhi[hidx + (size_t)t * DI] = __float2half_rn(hv);
    }
}

// ---------------- launch ----------------
extern "C" void kernel_launch(void* const* d_in, const int* in_sizes, int n_in,
                              void* d_out, int out_size) {
    const float* x     = (const float*)d_in[0];
    const float* W_hg  = (const float*)d_in[1];
    const float* W_out = (const float*)d_in[2];
    float* out = (float*)d_out;

    __half *hg_ptr, *xhi, *whgT, *woutT, *hhi;
    cudaGetSymbolAddress((void**)&hg_ptr, g_hg);
    cudaGetSymbolAddress((void**)&xhi, g_xhi);
    cudaGetSymbolAddress((void**)&whgT, g_whgT);
    cudaGetSymbolAddress((void**)&woutT, g_woutT);
    cudaGetSymbolAddress((void**)&hhi, g_hhi);

    cudaFuncSetAttribute(hmma_gemm<__half>, cudaFuncAttributeMaxDynamicSharedMemorySize, GEMM_DYNSMEM);
    cudaFuncSetAttribute(hmma_gemm<float>,  cudaFuncAttributeMaxDynamicSharedMemorySize, GEMM_DYNSMEM);

    cast_hi<<<(MROWS * DIM + 255) / 256, 256>>>(x, xhi, MROWS * DIM);
    {
        dim3 g1(HGCOLS / 32, DIM / 32);
        transpose_cast_tiled<1><<<g1, 256>>>(W_hg, whgT, DIM, HGCOLS);   // permuted
        dim3 g2(DIM / 32, DI / 32);
        transpose_cast_tiled<0><<<g2, 256>>>(W_out, woutT, DI, DIM);
    }

    // GEMM1: hg[16384,4096] = x @ W_hg   (fp16 output, interleaved h/g columns)
    {
        dim3 grid(HGCOLS / BN, MROWS / BM);
        hmma_gemm<__half><<<grid, 256, GEMM_DYNSMEM>>>(xhi, whgT, hg_ptr, HGCOLS, DIM);
    }

    scan_pass1<<<(NCH * NCHUNK) / 256, 256>>>();
    scan_mid<<<NCH / 256, 256>>>();
    scan_pass2<<<(NCH * NCHUNK) / 256, 256>>>();

    // GEMM2: out[16384,1024] = h @ W_out  (fp32 output)
    {
        dim3 grid(DIM / BN, MROWS / BM);
        hmma_gemm<float><<<grid, 256, GEMM_DYNSMEM>>>(hhi, woutT, out, DIM, DI);
    }
}

// round 16
// speedup vs baseline: 1.6267x; 1.0285x over previous
#include <cuda_runtime.h>
#include <cuda_fp16.h>
#include <math.h>
#include <stdint.h>

// ---------------- problem constants ----------------
#define BATCH   4
#define SEQ     4096
#define DIM     1024
#define DI      2048
#define HGCOLS  4096
#define MROWS   16384
#define NCH     8192
#define CHUNK   128
#define NCHUNK  32

// ---------------- scratch ----------------
__device__ __half g_hg[(size_t)MROWS * HGCOLS];       // 128 MB, interleaved (h,g) pairs
__device__ __half g_xhi[(size_t)MROWS * DIM];
__device__ __half g_whgT[(size_t)HGCOLS * DIM];       // [N,K], N-rows permuted for interleave
__device__ __half g_woutT[(size_t)DIM * DI];          // [N,K]
__device__ __half g_hhi[(size_t)MROWS * DI];
__device__ float g_P[NCH * NCHUNK];                   // chunk decay product
__device__ float g_B[NCH * NCHUNK];                   // chunk zero-state response
__device__ float g_W[NCH * NCHUNK];                   // chunk entry state

// ---------------- PTX helpers ----------------
__device__ __forceinline__ uint32_t smem_u32(const void* p) {
    uint32_t a;
    asm("{ .reg .u64 t; cvta.to.shared.u64 t, %1; cvt.u32.u64 %0, t; }" : "=r"(a) : "l"(p));
    return a;
}
__device__ __forceinline__ void cp16(uint32_t dst, const void* src) {
    asm volatile("cp.async.cg.shared.global [%0], [%1], 16;" :: "r"(dst), "l"(src));
}
#define CP_COMMIT() asm volatile("cp.async.commit_group;" ::: "memory")
#define CP_WAIT0()  asm volatile("cp.async.wait_group 0;" ::: "memory")

#define LDSM4(r, a) asm volatile( \
    "ldmatrix.sync.aligned.m8n8.x4.shared.b16 {%0,%1,%2,%3}, [%4];" \
    : "=r"((r)[0]), "=r"((r)[1]), "=r"((r)[2]), "=r"((r)[3]) : "r"(a))
#define LDSM2(r, a) asm volatile( \
    "ldmatrix.sync.aligned.m8n8.x2.shared.b16 {%0,%1}, [%2];" \
    : "=r"((r)[0]), "=r"((r)[1]) : "r"(a))
#define MMA16816(c, a, b) asm volatile( \
    "mma.sync.aligned.m16n8k16.row.col.f32.f16.f16.f32 " \
    "{%0,%1,%2,%3},{%4,%5,%6,%7},{%8,%9},{%0,%1,%2,%3};" \
    : "+f"((c)[0]), "+f"((c)[1]), "+f"((c)[2]), "+f"((c)[3]) \
    : "r"((a)[0]), "r"((a)[1]), "r"((a)[2]), "r"((a)[3]), "r"((b)[0]), "r"((b)[1]))

// ---------------- HMMA GEMM (R12-proven): C = A[M,K] @ B[N,K]^T, BK=64, 2-stage ----------------
#define BM 128
#define BN 128
#define BK 64
#define SSTRIDE_H 72                     // halves per smem row (64 + 8 pad)
#define LIMB_BYTES (128 * SSTRIDE_H * 2) // 18432
#define STAGE_BYTES (2 * LIMB_BYTES)     // A, B = 36864
#define GEMM_DYNSMEM (2 * STAGE_BYTES)   // 73728

template <typename OutT>
__global__ __launch_bounds__(256, 2)
void hmma_gemm(const __half* __restrict__ Ahi,
               const __half* __restrict__ Bhi,
               OutT* __restrict__ C, int N, int K) {
    extern __shared__ char dynsmem[];
    const uint32_t sbase = smem_u32(dynsmem);

    const int tid  = threadIdx.x;
    const int wid  = tid >> 5;
    const int lane = tid & 31;
    const int wm   = wid >> 2;
    const int wn   = wid & 3;
    const int m0   = blockIdx.y * BM;
    const int n0   = blockIdx.x * BN;
    const int NI   = K / BK;

    const int arow_l = (lane & 7) + ((lane & 8) ? 8 : 0);
    const int acol_l = (lane >> 4) * 8;
    const int blane  = lane & 15;
    const int brow_l = blane & 7;
    const int bcol_l = (blane >> 3) * 8;

    float acc[4][4][4];
    #pragma unroll
    for (int i = 0; i < 4; i++)
        #pragma unroll
        for (int j = 0; j < 4; j++)
            #pragma unroll
            for (int q = 0; q < 4; q++) acc[i][j][q] = 0.f;

    auto prefetch = [&](int it, int s) {
        const uint32_t sb = sbase + s * STAGE_BYTES;
        const int kt = it * BK;
        #pragma unroll
        for (int t = tid; t < 1024; t += 256) {
            const int row = t >> 3;
            const int seg = t & 7;
            const uint32_t so = (uint32_t)(row * (SSTRIDE_H * 2) + seg * 16);
            const size_t ga = (size_t)(m0 + row) * K + kt + seg * 8;
            const size_t gb = (size_t)(n0 + row) * K + kt + seg * 8;
            cp16(sb + so,              Ahi + ga);
            cp16(sb + LIMB_BYTES + so, Bhi + gb);
        }
        CP_COMMIT();
    };

    prefetch(0, 0);

    for (int it = 0; it < NI; it++) {
        const int s = it & 1;
        CP_WAIT0();
        __syncthreads();
        if (it + 1 < NI) prefetch(it + 1, s ^ 1);

        const uint32_t sAh = sbase + s * STAGE_BYTES;
        const uint32_t sBh = sAh + LIMB_BYTES;

        #pragma unroll
        for (int ks = 0; ks < 4; ks++) {
            uint32_t af[4][4], bh[4][2];
            #pragma unroll
            for (int mf = 0; mf < 4; mf++) {
                const uint32_t ao =
                    (uint32_t)((wm * 64 + mf * 16 + arow_l) * (SSTRIDE_H * 2) +
                               (ks * 16 + acol_l) * 2);
                LDSM4(af[mf], sAh + ao);
            }
            #pragma unroll
            for (int nf = 0; nf < 4; nf++) {
                const uint32_t bo =
                    (uint32_t)((wn * 32 + nf * 8 + brow_l) * (SSTRIDE_H * 2) +
                               (ks * 16 + bcol_l) * 2);
                LDSM2(bh[nf], sBh + bo);
            }
            #pragma unroll
            for (int mf = 0; mf < 4; mf++)
                #pragma unroll
                for (int nf = 0; nf < 4; nf++) MMA16816(acc[mf][nf], af[mf], bh[nf]);
        }
    }

    // epilogue
    #pragma unroll
    for (int mf = 0; mf < 4; mf++) {
        const int r0 = m0 + wm * 64 + mf * 16 + lane / 4;
        #pragma unroll
        for (int nf = 0; nf < 4; nf++) {
            const int col = n0 + wn * 32 + nf * 8 + 2 * (lane % 4);
            if (sizeof(OutT) == 4) {
                *(float2*)((float*)C + (size_t)r0 * N + col) =
                    make_float2(acc[mf][nf][0], acc[mf][nf][1]);
                *(float2*)((float*)C + (size_t)(r0 + 8) * N + col) =
                    make_float2(acc[mf][nf][2], acc[mf][nf][3]);
            } else {
                __half2 p0 = __float22half2_rn(make_float2(acc[mf][nf][0], acc[mf][nf][1]));
                __half2 p1 = __float22half2_rn(make_float2(acc[mf][nf][2], acc[mf][nf][3]));
                *(__half2*)((__half*)C + (size_t)r0 * N + col) = p0;
                *(__half2*)((__half*)C + (size_t)(r0 + 8) * N + col) = p1;
            }
        }
    }
}

// ---------------- prep ----------------
__global__ __launch_bounds__(256)
void cast_hi(const float* __restrict__ in, __half* __restrict__ hi, int n) {
    int i = blockIdx.x * blockDim.x + threadIdx.x;
    if (i >= n) return;
    hi[i] = __float2half_rn(in[i]);
}

// W[K,N] -> out[N,K] fp16. PERM: hidden col e -> row 2e, gate col e -> row 2e+1.
template <int PERM>
__global__ __launch_bounds__(256)
void transpose_cast_tiled(const float* __restrict__ W, __half* __restrict__ hi,
                          int K, int N) {
    __shared__ float tile[32][33];
    const int k0 = blockIdx.y * 32;
    const int n0 = blockIdx.x * 32;
    const int tx = threadIdx.x & 31;
    const int ty = threadIdx.x >> 5;

    #pragma unroll
    for (int r = 0; r < 4; r++) {
        const int k = k0 + ty + r * 8;
        tile[ty + r * 8][tx] = W[(size_t)k * N + n0 + tx];
    }
    __syncthreads();
    #pragma unroll
    for (int r = 0; r < 4; r++) {
        const int n = n0 + ty + r * 8;
        int p = n;
        if (PERM) p = (n < N / 2) ? (2 * n) : (2 * (n - N / 2) + 1);
        hi[(size_t)p * K + k0 + tx] = __float2half_rn(tile[tx][ty + r * 8]);
    }
}

// ---------------- scan: direct recurrence h = (1-z)h + z*v ----------------
__device__ __forceinline__ void minGRU_zv(float hid, float g, float& z, float& v) {
    z = __frcp_rn(1.f + __expf(-g));       // sigmoid(g)
    v = fmaxf(hid, 0.f) + 0.5f;            // relu + 0.5
}

__global__ __launch_bounds__(256)
void scan_pass1() {
    int tid = blockIdx.x * blockDim.x + threadIdx.x;
    int e = tid % DI;
    int c = (tid / DI) % NCHUNK;
    int b = tid / (DI * NCHUNK);

    const __half2* base =
        (const __half2*)(g_hg + ((size_t)(b * SEQ + c * CHUNK)) * HGCOLS + 2 * e);
    float P = 1.f, B = 0.f;
    #pragma unroll 4
    for (int t = 0; t < CHUNK; t++) {
        float2 hgv = __half22float2(__ldg(base + (size_t)t * (HGCOLS / 2)));
        float z, v;
        minGRU_zv(hgv.x, hgv.y, z, v);
        const float om = 1.f - z;
        P *= om;
        B = om * B + z * v;
    }
    int o = (b * NCHUNK + c) * DI + e;
    g_P[o] = P;
    g_B[o] = B;
}

__global__ __launch_bounds__(256)
void scan_mid() {
    int tid = blockIdx.x * blockDim.x + threadIdx.x;
    int e = tid % DI;
    int b = tid / DI;
    float W = 0.f;
    for (int c = 0; c < NCHUNK; c++) {
        int o = (b * NCHUNK + c) * DI + e;
        g_W[o] = W;
        W = g_P[o] * W + g_B[o];
    }
}

__global__ __launch_bounds__(256)
void scan_pass2() {
    int tid = blockIdx.x * blockDim.x + threadIdx.x;
    int e = tid % DI;
    int c = (tid / DI) % NCHUNK;
    int b = tid / (DI * NCHUNK);

    const __half2* base =
        (const __half2*)(g_hg + ((size_t)(b * SEQ + c * CHUNK)) * HGCOLS + 2 * e);
    size_t hidx = ((size_t)(b * SEQ + c * CHUNK)) * DI + e;
    float h = g_W[(b * NCHUNK + c) * DI + e];

    #pragma unroll 4
    for (int t = 0; t < CHUNK; t++) {
        float2 hgv = __half22float2(__ldg(base + (size_t)t * (HGCOLS / 2)));
        float z, v;
        minGRU_zv(hgv.x, hgv.y, z, v);
        h = (1.f - z) * h + z * v;
        g_hhi[hidx + (size_t)t * DI] = __float2half_rn(h);
    }
}

// ---------------- launch ----------------
extern "C" void kernel_launch(void* const* d_in, const int* in_sizes, int n_in,
                              void* d_out, int out_size) {
    const float* x     = (const float*)d_in[0];
    const float* W_hg  = (const float*)d_in[1];
    const float* W_out = (const float*)d_in[2];
    float* out = (float*)d_out;

    __half *hg_ptr, *xhi, *whgT, *woutT, *hhi;
    cudaGetSymbolAddress((void**)&hg_ptr, g_hg);
    cudaGetSymbolAddress((void**)&xhi, g_xhi);
    cudaGetSymbolAddress((void**)&whgT, g_whgT);
    cudaGetSymbolAddress((void**)&woutT, g_woutT);
    cudaGetSymbolAddress((void**)&hhi, g_hhi);

    cudaFuncSetAttribute(hmma_gemm<__half>, cudaFuncAttributeMaxDynamicSharedMemorySize, GEMM_DYNSMEM);
    cudaFuncSetAttribute(hmma_gemm<float>,  cudaFuncAttributeMaxDynamicSharedMemorySize, GEMM_DYNSMEM);

    cast_hi<<<(MROWS * DIM + 255) / 256, 256>>>(x, xhi, MROWS * DIM);
    {
        dim3 g1(HGCOLS / 32, DIM / 32);
        transpose_cast_tiled<1><<<g1, 256>>>(W_hg, whgT, DIM, HGCOLS);   // permuted
        dim3 g2(DIM / 32, DI / 32);
        transpose_cast_tiled<0><<<g2, 256>>>(W_out, woutT, DI, DIM);
    }

    // GEMM1: hg[16384,4096] = x @ W_hg   (fp16 output, interleaved h/g columns)
    {
        dim3 grid(HGCOLS / BN, MROWS / BM);
        hmma_gemm<__half><<<grid, 256, GEMM_DYNSMEM>>>(xhi, whgT, hg_ptr, HGCOLS, DIM);
    }

    scan_pass1<<<(NCH * NCHUNK) / 256, 256>>>();
    scan_mid<<<NCH / 256, 256>>>();
    scan_pass2<<<(NCH * NCHUNK) / 256, 256>>>();

    // GEMM2: out[16384,1024] = h @ W_out  (fp32 output)
    {
        dim3 grid(DIM / BN, MROWS / BM);
        hmma_gemm<float><<<grid, 256, GEMM_DYNSMEM>>>(hhi, woutT, out, DIM, DI);
    }
}

// round 17
// speedup vs baseline: 1.6505x; 1.0147x over previous
#include <cuda_runtime.h>
#include <cuda_fp16.h>
#include <math.h>
#include <stdint.h>

// ---------------- problem constants ----------------
#define BATCH   4
#define SEQ     4096
#define DIM     1024
#define DI      2048
#define HGCOLS  4096
#define MROWS   16384
#define NCH     8192
#define CHUNK   128
#define NCHUNK  32

// ---------------- scratch ----------------
__device__ __half g_hg[(size_t)MROWS * HGCOLS];       // 128 MB, interleaved (h,g) pairs
__device__ __half g_xhi[(size_t)MROWS * DIM];
__device__ __half g_whgT[(size_t)HGCOLS * DIM];       // [N,K], N-rows permuted for interleave
__device__ __half g_woutT[(size_t)DIM * DI];          // [N,K]
__device__ __half g_hhi[(size_t)MROWS * DI];
__device__ float g_P[NCH * NCHUNK];                   // chunk decay product
__device__ float g_B[NCH * NCHUNK];                   // chunk zero-state response
__device__ float g_W[NCH * NCHUNK];                   // chunk entry state

// ---------------- PTX helpers ----------------
__device__ __forceinline__ uint32_t smem_u32(const void* p) {
    uint32_t a;
    asm("{ .reg .u64 t; cvta.to.shared.u64 t, %1; cvt.u32.u64 %0, t; }" : "=r"(a) : "l"(p));
    return a;
}
__device__ __forceinline__ void cp16(uint32_t dst, const void* src) {
    asm volatile("cp.async.cg.shared.global [%0], [%1], 16;" :: "r"(dst), "l"(src));
}
#define CP_COMMIT() asm volatile("cp.async.commit_group;" ::: "memory")
#define CP_WAIT0()  asm volatile("cp.async.wait_group 0;" ::: "memory")

#define LDSM4(r, a) asm volatile( \
    "ldmatrix.sync.aligned.m8n8.x4.shared.b16 {%0,%1,%2,%3}, [%4];" \
    : "=r"((r)[0]), "=r"((r)[1]), "=r"((r)[2]), "=r"((r)[3]) : "r"(a))
#define LDSM2(r, a) asm volatile( \
    "ldmatrix.sync.aligned.m8n8.x2.shared.b16 {%0,%1}, [%2];" \
    : "=r"((r)[0]), "=r"((r)[1]) : "r"(a))
#define MMA16816(c, a, b) asm volatile( \
    "mma.sync.aligned.m16n8k16.row.col.f32.f16.f16.f32 " \
    "{%0,%1,%2,%3},{%4,%5,%6,%7},{%8,%9},{%0,%1,%2,%3};" \
    : "+f"((c)[0]), "+f"((c)[1]), "+f"((c)[2]), "+f"((c)[3]) \
    : "r"((a)[0]), "r"((a)[1]), "r"((a)[2]), "r"((a)[3]), "r"((b)[0]), "r"((b)[1]))

// ---------------- HMMA GEMM: C = A[M,K] @ B[N,K]^T, BK=64, 2-stage, phase-staggered K ----------------
#define BM 128
#define BN 128
#define BK 64
#define SSTRIDE_H 72                     // halves per smem row (64 + 8 pad)
#define LIMB_BYTES (128 * SSTRIDE_H * 2) // 18432
#define STAGE_BYTES (2 * LIMB_BYTES)     // A, B = 36864
#define GEMM_DYNSMEM (2 * STAGE_BYTES)   // 73728

template <typename OutT>
__global__ __launch_bounds__(256, 2)
void hmma_gemm(const __half* __restrict__ Ahi,
               const __half* __restrict__ Bhi,
               OutT* __restrict__ C, int N, int K) {
    extern __shared__ char dynsmem[];
    const uint32_t sbase = smem_u32(dynsmem);

    const int tid  = threadIdx.x;
    const int wid  = tid >> 5;
    const int lane = tid & 31;
    const int wm   = wid >> 2;
    const int wn   = wid & 3;
    const int m0   = blockIdx.y * BM;
    const int n0   = blockIdx.x * BN;
    const int NI   = K / BK;
    // Phase stagger: odd-bx CTAs start halfway through K and wrap. Co-resident
    // CTAs (adjacent bid) then alternate compute/memory phases instead of
    // convoying into the same wait+barrier instants.
    const int it0  = (blockIdx.x & 1) ? (NI >> 1) : 0;

    const int arow_l = (lane & 7) + ((lane & 8) ? 8 : 0);
    const int acol_l = (lane >> 4) * 8;
    const int blane  = lane & 15;
    const int brow_l = blane & 7;
    const int bcol_l = (blane >> 3) * 8;

    float acc[4][4][4];
    #pragma unroll
    for (int i = 0; i < 4; i++)
        #pragma unroll
        for (int j = 0; j < 4; j++)
            #pragma unroll
            for (int q = 0; q < 4; q++) acc[i][j][q] = 0.f;

    auto prefetch = [&](int chunk, int s) {
        const uint32_t sb = sbase + s * STAGE_BYTES;
        const int kt = chunk * BK;
        #pragma unroll
        for (int t = tid; t < 1024; t += 256) {
            const int row = t >> 3;
            const int seg = t & 7;
            const uint32_t so = (uint32_t)(row * (SSTRIDE_H * 2) + seg * 16);
            const size_t ga = (size_t)(m0 + row) * K + kt + seg * 8;
            const size_t gb = (size_t)(n0 + row) * K + kt + seg * 8;
            cp16(sb + so,              Ahi + ga);
            cp16(sb + LIMB_BYTES + so, Bhi + gb);
        }
        CP_COMMIT();
    };

    auto chunk_of = [&](int it) {
        int c = it0 + it;
        return (c >= NI) ? c - NI : c;
    };

    prefetch(chunk_of(0), 0);

    for (int it = 0; it < NI; it++) {
        const int s = it & 1;
        CP_WAIT0();
        __syncthreads();   // single barrier: stage s loaded AND stage s^1 free
        if (it + 1 < NI) prefetch(chunk_of(it + 1), s ^ 1);

        const uint32_t sAh = sbase + s * STAGE_BYTES;
        const uint32_t sBh = sAh + LIMB_BYTES;

        #pragma unroll
        for (int ks = 0; ks < 4; ks++) {
            uint32_t af[4][4], bh[4][2];
            #pragma unroll
            for (int mf = 0; mf < 4; mf++) {
                const uint32_t ao =
                    (uint32_t)((wm * 64 + mf * 16 + arow_l) * (SSTRIDE_H * 2) +
                               (ks * 16 + acol_l) * 2);
                LDSM4(af[mf], sAh + ao);
            }
            #pragma unroll
            for (int nf = 0; nf < 4; nf++) {
                const uint32_t bo =
                    (uint32_t)((wn * 32 + nf * 8 + brow_l) * (SSTRIDE_H * 2) +
                               (ks * 16 + bcol_l) * 2);
                LDSM2(bh[nf], sBh + bo);
            }
            #pragma unroll
            for (int mf = 0; mf < 4; mf++)
                #pragma unroll
                for (int nf = 0; nf < 4; nf++) MMA16816(acc[mf][nf], af[mf], bh[nf]);
        }
    }

    // epilogue
    #pragma unroll
    for (int mf = 0; mf < 4; mf++) {
        const int r0 = m0 + wm * 64 + mf * 16 + lane / 4;
        #pragma unroll
        for (int nf = 0; nf < 4; nf++) {
            const int col = n0 + wn * 32 + nf * 8 + 2 * (lane % 4);
            if (sizeof(OutT) == 4) {
                *(float2*)((float*)C + (size_t)r0 * N + col) =
                    make_float2(acc[mf][nf][0], acc[mf][nf][1]);
                *(float2*)((float*)C + (size_t)(r0 + 8) * N + col) =
                    make_float2(acc[mf][nf][2], acc[mf][nf][3]);
            } else {
                __half2 p0 = __float22half2_rn(make_float2(acc[mf][nf][0], acc[mf][nf][1]));
                __half2 p1 = __float22half2_rn(make_float2(acc[mf][nf][2], acc[mf][nf][3]));
                *(__half2*)((__half*)C + (size_t)r0 * N + col) = p0;
                *(__half2*)((__half*)C + (size_t)(r0 + 8) * N + col) = p1;
            }
        }
    }
}

// ---------------- prep ----------------
__global__ __launch_bounds__(256)
void cast_hi(const float* __restrict__ in, __half* __restrict__ hi, int n) {
    int i = blockIdx.x * blockDim.x + threadIdx.x;
    if (i >= n) return;
    hi[i] = __float2half_rn(in[i]);
}

// W[K,N] -> out[N,K] fp16. PERM: hidden col e -> row 2e, gate col e -> row 2e+1.
template <int PERM>
__global__ __launch_bounds__(256)
void transpose_cast_tiled(const float* __restrict__ W, __half* __restrict__ hi,
                          int K, int N) {
    __shared__ float tile[32][33];
    const int k0 = blockIdx.y * 32;
    const int n0 = blockIdx.x * 32;
    const int tx = threadIdx.x & 31;
    const int ty = threadIdx.x >> 5;

    #pragma unroll
    for (int r = 0; r < 4; r++) {
        const int k = k0 + ty + r * 8;
        tile[ty + r * 8][tx] = W[(size_t)k * N + n0 + tx];
    }
    __syncthreads();
    #pragma unroll
    for (int r = 0; r < 4; r++) {
        const int n = n0 + ty + r * 8;
        int p = n;
        if (PERM) p = (n < N / 2) ? (2 * n) : (2 * (n - N / 2) + 1);
        hi[(size_t)p * K + k0 + tx] = __float2half_rn(tile[tx][ty + r * 8]);
    }
}

// ---------------- scan: direct recurrence h = (1-z)h + z*v ----------------
__device__ __forceinline__ void minGRU_zv(float hid, float g, float& z, float& v) {
    z = __frcp_rn(1.f + __expf(-g));       // sigmoid(g)
    v = fmaxf(hid, 0.f) + 0.5f;            // relu + 0.5
}

__global__ __launch_bounds__(256)
void scan_pass1() {
    int tid = blockIdx.x * blockDim.x + threadIdx.x;
    int e = tid % DI;
    int c = (tid / DI) % NCHUNK;
    int b = tid / (DI * NCHUNK);

    const __half2* base =
        (const __half2*)(g_hg + ((size_t)(b * SEQ + c * CHUNK)) * HGCOLS + 2 * e);
    float P = 1.f, B = 0.f;
    #pragma unroll 4
    for (int t = 0; t < CHUNK; t++) {
        float2 hgv = __half22float2(__ldg(base + (size_t)t * (HGCOLS / 2)));
        float z, v;
        minGRU_zv(hgv.x, hgv.y, z, v);
        const float om = 1.f - z;
        P *= om;
        B = om * B + z * v;
    }
    int o = (b * NCHUNK + c) * DI + e;
    g_P[o] = P;
    g_B[o] = B;
}

__global__ __launch_bounds__(256)
void scan_mid() {
    int tid = blockIdx.x * blockDim.x + threadIdx.x;
    int e = tid % DI;
    int b = tid / DI;
    float W = 0.f;
    for (int c = 0; c < NCHUNK; c++) {
        int o = (b * NCHUNK + c) * DI + e;
        g_W[o] = W;
        W = g_P[o] * W + g_B[o];
    }
}

__global__ __launch_bounds__(256)
void scan_pass2() {
    int tid = blockIdx.x * blockDim.x + threadIdx.x;
    int e = tid % DI;
    int c = (tid / DI) % NCHUNK;
    int b = tid / (DI * NCHUNK);

    const __half2* base =
        (const __half2*)(g_hg + ((size_t)(b * SEQ + c * CHUNK)) * HGCOLS + 2 * e);
    size_t hidx = ((size_t)(b * SEQ + c * CHUNK)) * DI + e;
    float h = g_W[(b * NCHUNK + c) * DI + e];

    #pragma unroll 4
    for (int t = 0; t < CHUNK; t++) {
        float2 hgv = __half22float2(__ldg(base + (size_t)t * (HGCOLS / 2)));
        float z, v;
        minGRU_zv(hgv.x, hgv.y, z, v);
        h = (1.f - z) * h + z * v;
        g_hhi[hidx + (size_t)t * DI] = __float2half_rn(h);
    }
}

// ---------------- launch ----------------
extern "C" void kernel_launch(void* const* d_in, const int* in_sizes, int n_in,
                              void* d_out, int out_size) {
    const float* x     = (const float*)d_in[0];
    const float* W_hg  = (const float*)d_in[1];
    const float* W_out = (const float*)d_in[2];
    float* out = (float*)d_out;

    __half *hg_ptr, *xhi, *whgT, *woutT, *hhi;
    cudaGetSymbolAddress((void**)&hg_ptr, g_hg);
    cudaGetSymbolAddress((void**)&xhi, g_xhi);
    cudaGetSymbolAddress((void**)&whgT, g_whgT);
    cudaGetSymbolAddress((void**)&woutT, g_woutT);
    cudaGetSymbolAddress((void**)&hhi, g_hhi);

    cudaFuncSetAttribute(hmma_gemm<__half>, cudaFuncAttributeMaxDynamicSharedMemorySize, GEMM_DYNSMEM);
    cudaFuncSetAttribute(hmma_gemm<float>,  cudaFuncAttributeMaxDynamicSharedMemorySize, GEMM_DYNSMEM);

    cast_hi<<<(MROWS * DIM + 255) / 256, 256>>>(x, xhi, MROWS * DIM);
    {
        dim3 g1(HGCOLS / 32, DIM / 32);
        transpose_cast_tiled<1><<<g1, 256>>>(W_hg, whgT, DIM, HGCOLS);   // permuted
        dim3 g2(DIM / 32, DI / 32);
        transpose_cast_tiled<0><<<g2, 256>>>(W_out, woutT, DI, DIM);
    }

    // GEMM1: hg[16384,4096] = x @ W_hg   (fp16 output, interleaved h/g columns)
    {
        dim3 grid(HGCOLS / BN, MROWS / BM);
        hmma_gemm<__half><<<grid, 256, GEMM_DYNSMEM>>>(xhi, whgT, hg_ptr, HGCOLS, DIM);
    }

    scan_pass1<<<(NCH * NCHUNK) / 256, 256>>>();
    scan_mid<<<NCH / 256, 256>>>();
    scan_pass2<<<(NCH * NCHUNK) / 256, 256>>>();

    // GEMM2: out[16384,1024] = h @ W_out  (fp32 output)
    {
        dim3 grid(DIM / BN, MROWS / BM);
        hmma_gemm<float><<<grid, 256, GEMM_DYNSMEM>>>(hhi, woutT, out, DIM, DI);
    }
}